// round 3
// baseline (speedup 1.0000x reference)
#include <cuda_runtime.h>
#include <cuda_bf16.h>

// Problem constants
#define BB 8
#define NN 128
#define CC 3
#define FF 64
#define KK 64

// Scratch for projections: p[row][kk], row = (b*N+n)*C+c (3072 rows), kk in [0,128):
// kk<64 -> p_i (w_i half), kk>=64 -> p_j (w_j half).
__device__ float g_p[BB * NN * CC * 128];

// ---------------------------------------------------------------------------
// Kernel 1: p[row][kk] = sum_f vf[row][f] * ws[f][kk]
//   where ws[f][kk] = (kk<64) ? w_vs[f][kk] : w_vs[64+f][kk-64]
// 96 blocks x 256 threads; 32 rows per block.
// ---------------------------------------------------------------------------
__global__ __launch_bounds__(256)
void proj_kernel(const float* __restrict__ vf, const float* __restrict__ w)
{
    __shared__ float ws[FF * 128];   // 32 KB: rearranged weights [f][kk]
    __shared__ float vfs[32 * FF];   // 8 KB: this block's 32 vf rows

    const int tid = threadIdx.x;

    // Load + rearrange weights
    #pragma unroll
    for (int idx = tid; idx < FF * 128; idx += 256) {
        int f  = idx >> 7;
        int kk = idx & 127;
        ws[idx] = (kk < 64) ? w[f * 64 + kk] : w[(64 + f) * 64 + (kk - 64)];
    }

    // Stage 32 contiguous vf rows (row-major, contiguous in gmem)
    const int r0 = blockIdx.x * 32;
    const float4* vf4 = reinterpret_cast<const float4*>(vf + (size_t)r0 * FF);
    float4* vfs4 = reinterpret_cast<float4*>(vfs);
    #pragma unroll
    for (int idx = tid; idx < 32 * (FF / 4); idx += 256)
        vfs4[idx] = vf4[idx];

    __syncthreads();

    const int kg = tid & 31;   // float4 group over kk (32 groups x 4 = 128)
    const int rv = tid >> 5;   // 0..7 ; handles rows rv, rv+8, rv+16, rv+24

    float4 acc0 = make_float4(0.f, 0.f, 0.f, 0.f);
    float4 acc1 = acc0, acc2 = acc0, acc3 = acc0;

    const float4* ws4 = reinterpret_cast<const float4*>(ws); // [64][32]

    #pragma unroll 8
    for (int f = 0; f < FF; ++f) {
        float4 w4 = ws4[f * 32 + kg];
        float v0 = vfs[(rv     ) * FF + f];
        float v1 = vfs[(rv +  8) * FF + f];
        float v2 = vfs[(rv + 16) * FF + f];
        float v3 = vfs[(rv + 24) * FF + f];
        acc0.x += v0 * w4.x; acc0.y += v0 * w4.y; acc0.z += v0 * w4.z; acc0.w += v0 * w4.w;
        acc1.x += v1 * w4.x; acc1.y += v1 * w4.y; acc1.z += v1 * w4.z; acc1.w += v1 * w4.w;
        acc2.x += v2 * w4.x; acc2.y += v2 * w4.y; acc2.z += v2 * w4.z; acc2.w += v2 * w4.w;
        acc3.x += v3 * w4.x; acc3.y += v3 * w4.y; acc3.z += v3 * w4.z; acc3.w += v3 * w4.w;
    }

    float4* p4 = reinterpret_cast<float4*>(g_p); // [3072][32]
    p4[(size_t)(r0 + rv     ) * 32 + kg] = acc0;
    p4[(size_t)(r0 + rv +  8) * 32 + kg] = acc1;
    p4[(size_t)(r0 + rv + 16) * 32 + kg] = acc2;
    p4[(size_t)(r0 + rv + 24) * 32 + kg] = acc3;
}

// ---------------------------------------------------------------------------
// Kernel 2: out[b,i,j,k] = relu( sum_c d[b,i,j,c] * (p_i[b,i,c,k] + p_j[b,j,c,k])
//                                + (sum_c d[b,i,j,c]) * b_vs[k] )
// grid (jhalf=2, itile=16, b=8) x 256 threads.
// Each block: 8 i-values x 64 j-values; thread = (kq in 0..15 [float4 k], jl in 0..15).
// p_i held in registers per i; p_j re-served from L1 across the 8 i iterations.
// ---------------------------------------------------------------------------
__global__ __launch_bounds__(256)
void fuse_kernel(const float* __restrict__ dist,
                 const float* __restrict__ bvs,
                 float* __restrict__ out)
{
    const int kq = threadIdx.x & 15;   // k quad: k = kq*4
    const int jl = threadIdx.x >> 4;   // 0..15
    const int j0 = blockIdx.x * 64;    // j half
    const int i0 = blockIdx.y * 8;     // i tile
    const int b  = blockIdx.z;

    const float4* p4 = reinterpret_cast<const float4*>(g_p); // [3072][32]
    const float4 bv = reinterpret_cast<const float4*>(bvs)[kq];

    #pragma unroll 2
    for (int ii = 0; ii < 8; ++ii) {
        const int i = i0 + ii;
        const int rowi = (b * NN + i) * CC;
        const float4 pi0 = p4[(size_t)(rowi    ) * 32 + kq];
        const float4 pi1 = p4[(size_t)(rowi + 1) * 32 + kq];
        const float4 pi2 = p4[(size_t)(rowi + 2) * 32 + kq];

        const float* drow = dist + (size_t)(b * NN + i) * NN * CC;
        float4* orow = reinterpret_cast<float4*>(out + (size_t)(b * NN + i) * NN * KK);

        #pragma unroll
        for (int jt = 0; jt < 4; ++jt) {
            const int j = j0 + jl + jt * 16;
            const float d0 = __ldg(drow + j * 3 + 0);
            const float d1 = __ldg(drow + j * 3 + 1);
            const float d2 = __ldg(drow + j * 3 + 2);
            const int rowj = (b * NN + j) * CC;
            const float4 pj0 = p4[(size_t)(rowj    ) * 32 + 16 + kq];
            const float4 pj1 = p4[(size_t)(rowj + 1) * 32 + 16 + kq];
            const float4 pj2 = p4[(size_t)(rowj + 2) * 32 + 16 + kq];
            const float ds = d0 + d1 + d2;

            float4 a;
            a.x = ds * bv.x + d0 * (pi0.x + pj0.x) + d1 * (pi1.x + pj1.x) + d2 * (pi2.x + pj2.x);
            a.y = ds * bv.y + d0 * (pi0.y + pj0.y) + d1 * (pi1.y + pj1.y) + d2 * (pi2.y + pj2.y);
            a.z = ds * bv.z + d0 * (pi0.z + pj0.z) + d1 * (pi1.z + pj1.z) + d2 * (pi2.z + pj2.z);
            a.w = ds * bv.w + d0 * (pi0.w + pj0.w) + d1 * (pi1.w + pj1.w) + d2 * (pi2.w + pj2.w);

            a.x = fmaxf(a.x, 0.f);
            a.y = fmaxf(a.y, 0.f);
            a.z = fmaxf(a.z, 0.f);
            a.w = fmaxf(a.w, 0.f);

            orow[(size_t)j * 16 + kq] = a;
        }
    }
}

extern "C" void kernel_launch(void* const* d_in, const int* in_sizes, int n_in,
                              void* d_out, int out_size)
{
    const float* vf   = (const float*)d_in[0]; // (8,128,3,64)
    const float* dist = (const float*)d_in[1]; // (8,128,128,3)
    const float* w_vs = (const float*)d_in[2]; // (128,64)
    const float* b_vs = (const float*)d_in[3]; // (64,)
    float* out = (float*)d_out;                // (8,128,128,64)

    (void)in_sizes; (void)n_in; (void)out_size;

    proj_kernel<<<96, 256>>>(vf, w_vs);
    fuse_kernel<<<dim3(2, 16, 8), 256>>>(dist, b_vs, out);
}

// round 4
// speedup vs baseline: 1.0804x; 1.0804x over previous
#include <cuda_runtime.h>
#include <cuda_bf16.h>

// Problem constants
#define BB 8
#define NN 128
#define CC 3
#define FF 64
#define KK 64

// Scratch for projections: p[row][kk], row = (b*N+n)*C+c (3072 rows), kk in [0,128):
// kk<64 -> p_i (w_i half), kk>=64 -> p_j (w_j half).
__device__ float g_p[BB * NN * CC * 128];

// ---------------------------------------------------------------------------
// Kernel 1: p[row][kk] = sum_f vf[row][f] * ws[f][kk]
//   where ws[f][kk] = (kk<64) ? w_vs[f][kk] : w_vs[64+f][kk-64]
// 96 blocks x 256 threads; 32 rows per block.
// ---------------------------------------------------------------------------
__global__ __launch_bounds__(256)
void proj_kernel(const float* __restrict__ vf, const float* __restrict__ w)
{
    __shared__ float ws[FF * 128];   // 32 KB: rearranged weights [f][kk]
    __shared__ float vfs[32 * FF];   // 8 KB: this block's 32 vf rows

    const int tid = threadIdx.x;

    // Load + rearrange weights
    #pragma unroll
    for (int idx = tid; idx < FF * 128; idx += 256) {
        int f  = idx >> 7;
        int kk = idx & 127;
        ws[idx] = (kk < 64) ? w[f * 64 + kk] : w[(64 + f) * 64 + (kk - 64)];
    }

    // Stage 32 contiguous vf rows (row-major, contiguous in gmem)
    const int r0 = blockIdx.x * 32;
    const float4* vf4 = reinterpret_cast<const float4*>(vf + (size_t)r0 * FF);
    float4* vfs4 = reinterpret_cast<float4*>(vfs);
    #pragma unroll
    for (int idx = tid; idx < 32 * (FF / 4); idx += 256)
        vfs4[idx] = vf4[idx];

    __syncthreads();

    const int kg = tid & 31;   // float4 group over kk (32 groups x 4 = 128)
    const int rv = tid >> 5;   // 0..7 ; handles rows rv, rv+8, rv+16, rv+24

    float4 acc0 = make_float4(0.f, 0.f, 0.f, 0.f);
    float4 acc1 = acc0, acc2 = acc0, acc3 = acc0;

    const float4* ws4 = reinterpret_cast<const float4*>(ws); // [64][32]

    #pragma unroll 8
    for (int f = 0; f < FF; ++f) {
        float4 w4 = ws4[f * 32 + kg];
        float v0 = vfs[(rv     ) * FF + f];
        float v1 = vfs[(rv +  8) * FF + f];
        float v2 = vfs[(rv + 16) * FF + f];
        float v3 = vfs[(rv + 24) * FF + f];
        acc0.x += v0 * w4.x; acc0.y += v0 * w4.y; acc0.z += v0 * w4.z; acc0.w += v0 * w4.w;
        acc1.x += v1 * w4.x; acc1.y += v1 * w4.y; acc1.z += v1 * w4.z; acc1.w += v1 * w4.w;
        acc2.x += v2 * w4.x; acc2.y += v2 * w4.y; acc2.z += v2 * w4.z; acc2.w += v2 * w4.w;
        acc3.x += v3 * w4.x; acc3.y += v3 * w4.y; acc3.z += v3 * w4.z; acc3.w += v3 * w4.w;
    }

    float4* p4 = reinterpret_cast<float4*>(g_p); // [3072][32]
    p4[(size_t)(r0 + rv     ) * 32 + kg] = acc0;
    p4[(size_t)(r0 + rv +  8) * 32 + kg] = acc1;
    p4[(size_t)(r0 + rv + 16) * 32 + kg] = acc2;
    p4[(size_t)(r0 + rv + 24) * 32 + kg] = acc3;
}

// ---------------------------------------------------------------------------
// Kernel 2: out[b,i,j,k] = relu( sum_c d[b,i,j,c] * (p_i[b,i,c,k] + p_j[b,j,c,k])
//                                + (sum_c d[b,i,j,c]) * b_vs[k] )
// grid (jg=8, it=16, b=8) = 1024 blocks x 256 threads.
// Block covers 8 i-values x 16 j-values. Thread = (kq in 0..15, jl in 0..15):
// one j per thread; p_j held in REGISTERS across the 8-i loop (p_j depends
// only on j). Per i-iteration: 3 broadcast p_i float4 loads + 3 broadcast
// dist scalars + 12 FMAs + 1 float4 store.
// ---------------------------------------------------------------------------
__global__ __launch_bounds__(256, 4)
void fuse_kernel(const float* __restrict__ dist,
                 const float* __restrict__ bvs,
                 float* __restrict__ out)
{
    const int kq = threadIdx.x & 15;   // k quad: k = kq*4
    const int jl = threadIdx.x >> 4;   // 0..15
    const int j  = blockIdx.x * 16 + jl;
    const int i0 = blockIdx.y * 8;
    const int b  = blockIdx.z;

    const float4* p4 = reinterpret_cast<const float4*>(g_p); // [3072][32]
    const float4 bv = reinterpret_cast<const float4*>(bvs)[kq];

    // p_j: held in registers for the whole block lifetime
    const int rowj = (b * NN + j) * CC;
    const float4 pj0 = p4[(size_t)(rowj    ) * 32 + 16 + kq];
    const float4 pj1 = p4[(size_t)(rowj + 1) * 32 + 16 + kq];
    const float4 pj2 = p4[(size_t)(rowj + 2) * 32 + 16 + kq];

    const float* dbase = dist + ((size_t)(b * NN + i0) * NN + j) * CC;
    float4* obase = reinterpret_cast<float4*>(out)
                  + ((size_t)(b * NN + i0) * NN + j) * 16 + kq;

    #pragma unroll
    for (int ii = 0; ii < 8; ++ii) {
        const int rowi = (b * NN + i0 + ii) * CC;
        const float4 pi0 = p4[(size_t)(rowi    ) * 32 + kq];
        const float4 pi1 = p4[(size_t)(rowi + 1) * 32 + kq];
        const float4 pi2 = p4[(size_t)(rowi + 2) * 32 + kq];

        const float* dp = dbase + (size_t)ii * NN * CC;
        const float d0 = __ldg(dp + 0);
        const float d1 = __ldg(dp + 1);
        const float d2 = __ldg(dp + 2);
        const float ds = d0 + d1 + d2;

        float4 a;
        a.x = ds * bv.x + d0 * (pi0.x + pj0.x) + d1 * (pi1.x + pj1.x) + d2 * (pi2.x + pj2.x);
        a.y = ds * bv.y + d0 * (pi0.y + pj0.y) + d1 * (pi1.y + pj1.y) + d2 * (pi2.y + pj2.y);
        a.z = ds * bv.z + d0 * (pi0.z + pj0.z) + d1 * (pi1.z + pj1.z) + d2 * (pi2.z + pj2.z);
        a.w = ds * bv.w + d0 * (pi0.w + pj0.w) + d1 * (pi1.w + pj1.w) + d2 * (pi2.w + pj2.w);

        a.x = fmaxf(a.x, 0.f);
        a.y = fmaxf(a.y, 0.f);
        a.z = fmaxf(a.z, 0.f);
        a.w = fmaxf(a.w, 0.f);

        obase[(size_t)ii * NN * 16] = a;
    }
}

extern "C" void kernel_launch(void* const* d_in, const int* in_sizes, int n_in,
                              void* d_out, int out_size)
{
    const float* vf   = (const float*)d_in[0]; // (8,128,3,64)
    const float* dist = (const float*)d_in[1]; // (8,128,128,3)
    const float* w_vs = (const float*)d_in[2]; // (128,64)
    const float* b_vs = (const float*)d_in[3]; // (64,)
    float* out = (float*)d_out;                // (8,128,128,64)

    (void)in_sizes; (void)n_in; (void)out_size;

    proj_kernel<<<96, 256>>>(vf, w_vs);
    fuse_kernel<<<dim3(8, 16, 8), 256>>>(dist, b_vs, out);
}

// round 5
// speedup vs baseline: 1.2457x; 1.1530x over previous
#include <cuda_runtime.h>
#include <cuda_bf16.h>

// Problem constants
#define BB 8
#define NN 128
#define CC 3
#define FF 64
#define KK 64

// Scratch for projections: p[row][kk], row = (b*N+n)*C+c (3072 rows), kk in [0,128):
// kk<64 -> p_i (w_i half), kk>=64 -> p_j (w_j half).
__device__ float g_p[BB * NN * CC * 128];

// ---------------------------------------------------------------------------
// Kernel 1: p[row][kk] = sum_f vf[row][f] * ws[f][kk]
//   where ws[f][kk] = (kk<64) ? w_vs[f][kk] : w_vs[64+f][kk-64]
// 96 blocks x 256 threads; 32 rows per block.
// ---------------------------------------------------------------------------
__global__ __launch_bounds__(256)
void proj_kernel(const float* __restrict__ vf, const float* __restrict__ w)
{
    __shared__ float ws[FF * 128];   // 32 KB: rearranged weights [f][kk]
    __shared__ float vfs[32 * FF];   // 8 KB: this block's 32 vf rows

    const int tid = threadIdx.x;

    // Load + rearrange weights
    #pragma unroll
    for (int idx = tid; idx < FF * 128; idx += 256) {
        int f  = idx >> 7;
        int kk = idx & 127;
        ws[idx] = (kk < 64) ? w[f * 64 + kk] : w[(64 + f) * 64 + (kk - 64)];
    }

    // Stage 32 contiguous vf rows (row-major, contiguous in gmem)
    const int r0 = blockIdx.x * 32;
    const float4* vf4 = reinterpret_cast<const float4*>(vf + (size_t)r0 * FF);
    float4* vfs4 = reinterpret_cast<float4*>(vfs);
    #pragma unroll
    for (int idx = tid; idx < 32 * (FF / 4); idx += 256)
        vfs4[idx] = vf4[idx];

    __syncthreads();

    const int kg = tid & 31;   // float4 group over kk (32 groups x 4 = 128)
    const int rv = tid >> 5;   // 0..7 ; handles rows rv, rv+8, rv+16, rv+24

    float4 acc0 = make_float4(0.f, 0.f, 0.f, 0.f);
    float4 acc1 = acc0, acc2 = acc0, acc3 = acc0;

    const float4* ws4 = reinterpret_cast<const float4*>(ws); // [64][32]

    #pragma unroll 8
    for (int f = 0; f < FF; ++f) {
        float4 w4 = ws4[f * 32 + kg];
        float v0 = vfs[(rv     ) * FF + f];
        float v1 = vfs[(rv +  8) * FF + f];
        float v2 = vfs[(rv + 16) * FF + f];
        float v3 = vfs[(rv + 24) * FF + f];
        acc0.x += v0 * w4.x; acc0.y += v0 * w4.y; acc0.z += v0 * w4.z; acc0.w += v0 * w4.w;
        acc1.x += v1 * w4.x; acc1.y += v1 * w4.y; acc1.z += v1 * w4.z; acc1.w += v1 * w4.w;
        acc2.x += v2 * w4.x; acc2.y += v2 * w4.y; acc2.z += v2 * w4.z; acc2.w += v2 * w4.w;
        acc3.x += v3 * w4.x; acc3.y += v3 * w4.y; acc3.z += v3 * w4.z; acc3.w += v3 * w4.w;
    }

    float4* p4 = reinterpret_cast<float4*>(g_p); // [3072][32]
    p4[(size_t)(r0 + rv     ) * 32 + kg] = acc0;
    p4[(size_t)(r0 + rv +  8) * 32 + kg] = acc1;
    p4[(size_t)(r0 + rv + 16) * 32 + kg] = acc2;
    p4[(size_t)(r0 + rv + 24) * 32 + kg] = acc3;
}

// ---------------------------------------------------------------------------
// Kernel 2: out[b,i,j,k] = relu( sum_c d[b,i,j,c] * (p_i[b,i,c,k] + p_j[b,j,c,k])
//                                + (sum_c d[b,i,j,c]) * b_vs[k] )
// grid (jg=8, it=16, b=8) = 1024 blocks x 256 threads; block = 8 i x 16 j.
// Stage phase: p_i tile (6 KB) + dist tile (1.5 KB) -> smem in one coalesced
// burst; p_j -> registers (overlapped with the burst). Main loop: LDS + FMA +
// STG only — no gmem read latency on the critical path.
// ---------------------------------------------------------------------------
__global__ __launch_bounds__(256, 6)
void fuse_kernel(const float* __restrict__ dist,
                 const float* __restrict__ bvs,
                 float* __restrict__ out)
{
    __shared__ float4 pi_s[8 * 3 * 16];   // [ii*3+c][kq]  6 KB
    __shared__ float  dist_s[8 * 48];     // [ii][jl*3+c]  1.5 KB

    const int tid = threadIdx.x;
    const int kq  = tid & 15;   // k quad: k = kq*4
    const int jl  = tid >> 4;   // 0..15
    const int j0  = blockIdx.x * 16;
    const int i0  = blockIdx.y * 8;
    const int b   = blockIdx.z;

    const float4* p4 = reinterpret_cast<const float4*>(g_p); // [3072][32]
    const int rowbase = (b * NN + i0) * CC;                  // 24 consecutive rows

    // Stage p_i: 384 float4 (rows rowbase..rowbase+23, first 16 float4 of each)
    {
        const int r = tid >> 4, kk = tid & 15;
        pi_s[tid] = p4[(size_t)(rowbase + r) * 32 + kk];
        if (tid < 128) {
            const int idx2 = tid + 256;
            const int r2 = idx2 >> 4, kk2 = idx2 & 15;
            pi_s[idx2] = p4[(size_t)(rowbase + r2) * 32 + kk2];
        }
    }
    // Stage dist: 96 float4 (8 rows x 48 floats, 16B-aligned: 48*jg % 4 == 0)
    if (tid < 96) {
        const int ii = tid / 12, q = tid % 12;
        const float4* d4 = reinterpret_cast<const float4*>(
            dist + (size_t)(b * NN + i0 + ii) * NN * CC + j0 * CC);
        reinterpret_cast<float4*>(dist_s)[ii * 12 + q] = d4[q];
    }

    // p_j in registers (issued before the sync; overlaps the staging burst)
    const int j = j0 + jl;
    const int rowj = (b * NN + j) * CC;
    const float4 pj0 = p4[(size_t)(rowj    ) * 32 + 16 + kq];
    const float4 pj1 = p4[(size_t)(rowj + 1) * 32 + 16 + kq];
    const float4 pj2 = p4[(size_t)(rowj + 2) * 32 + 16 + kq];
    const float4 bv  = reinterpret_cast<const float4*>(bvs)[kq];

    __syncthreads();

    float4* obase = reinterpret_cast<float4*>(out)
                  + ((size_t)(b * NN + i0) * NN + j) * 16 + kq;

    #pragma unroll
    for (int ii = 0; ii < 8; ++ii) {
        const float4 pi0 = pi_s[(ii * 3 + 0) * 16 + kq];
        const float4 pi1 = pi_s[(ii * 3 + 1) * 16 + kq];
        const float4 pi2 = pi_s[(ii * 3 + 2) * 16 + kq];
        const float d0 = dist_s[ii * 48 + jl * 3 + 0];
        const float d1 = dist_s[ii * 48 + jl * 3 + 1];
        const float d2 = dist_s[ii * 48 + jl * 3 + 2];
        const float ds = d0 + d1 + d2;

        float4 a;
        a.x = ds * bv.x + d0 * (pi0.x + pj0.x) + d1 * (pi1.x + pj1.x) + d2 * (pi2.x + pj2.x);
        a.y = ds * bv.y + d0 * (pi0.y + pj0.y) + d1 * (pi1.y + pj1.y) + d2 * (pi2.y + pj2.y);
        a.z = ds * bv.z + d0 * (pi0.z + pj0.z) + d1 * (pi1.z + pj1.z) + d2 * (pi2.z + pj2.z);
        a.w = ds * bv.w + d0 * (pi0.w + pj0.w) + d1 * (pi1.w + pj1.w) + d2 * (pi2.w + pj2.w);

        a.x = fmaxf(a.x, 0.f);
        a.y = fmaxf(a.y, 0.f);
        a.z = fmaxf(a.z, 0.f);
        a.w = fmaxf(a.w, 0.f);

        obase[(size_t)ii * NN * 16] = a;
    }
}

extern "C" void kernel_launch(void* const* d_in, const int* in_sizes, int n_in,
                              void* d_out, int out_size)
{
    const float* vf   = (const float*)d_in[0]; // (8,128,3,64)
    const float* dist = (const float*)d_in[1]; // (8,128,128,3)
    const float* w_vs = (const float*)d_in[2]; // (128,64)
    const float* b_vs = (const float*)d_in[3]; // (64,)
    float* out = (float*)d_out;                // (8,128,128,64)

    (void)in_sizes; (void)n_in; (void)out_size;

    proj_kernel<<<96, 256>>>(vf, w_vs);
    fuse_kernel<<<dim3(8, 16, 8), 256>>>(dist, b_vs, out);
}